// round 2
// baseline (speedup 1.0000x reference)
#include <cuda_runtime.h>
#include <cstdint>

#define BATCH 8
#define CH    16
#define HH    256
#define WW    256
#define NPTS  (BATCH*HH*WW)            // 524288 grid points
#define SCRATCH_F4 (NPTS*4)            // [b][i][j][c] as float4 quads: 2,097,152 float4 = 33.5 MB

// Scratch accumulator, channels innermost: scratch[b][i][j][c], c = 16 floats = 4 float4.
// __device__ global (no runtime allocation) — 16B aligned by float4 type.
__device__ float4 g_scratch4[SCRATCH_F4];

// ---------------------------------------------------------------------------
// Kernel 1: zero the scratch accumulator (and pull it into L2).
// ---------------------------------------------------------------------------
__global__ void __launch_bounds__(256) zero_kernel() {
    int idx = blockIdx.x * blockDim.x + threadIdx.x;   // 0 .. SCRATCH_F4-1
    g_scratch4[idx] = make_float4(0.f, 0.f, 0.f, 0.f);
}

// ---------------------------------------------------------------------------
// Kernel 2: scatter. One thread per (b,h,w) grid point.
//   g = (inv_grid+1)*0.5; ci = clip(g0*H + 1, 0, H+1-2eps); i0 = floor(ci).
//   Taps land at output rows/cols (i0+di-1, j0+dj-1); only >=256 falls outside
//   the crop (ci >= 1 always), so a single unsigned upper-bound check suffices.
//   Scatter x[b,:,h,w] * wi*wj into scratch[b][oi][oj][:] via 4x float4 atomics.
// ---------------------------------------------------------------------------
__global__ void __launch_bounds__(256) scatter_kernel(
    const float* __restrict__ x, const float2* __restrict__ grid)
{
    int idx = blockIdx.x * blockDim.x + threadIdx.x;   // 0 .. NPTS-1
    int b  = idx >> 16;
    int hw = idx & 0xFFFF;

    float2 g = grid[idx];   // g.x -> row coordinate, g.y -> col coordinate

    float ci = fminf(fmaxf((g.x + 1.0f) * 0.5f * 256.0f + 1.0f, 0.0f), 257.0f);
    float cj = fminf(fmaxf((g.y + 1.0f) * 0.5f * 256.0f + 1.0f, 0.0f), 257.0f);

    float fi0 = floorf(ci), fj0 = floorf(cj);
    int   i0 = (int)fi0,    j0 = (int)fj0;
    float fi = ci - fi0,    fj = cj - fj0;          // in [0,1)

    float wi[2] = {1.0f - fi, fi};
    float wj[2] = {1.0f - fj, fj};

    // Load the 16-channel pixel (each load is warp-coalesced: consecutive w).
    const float* xp = x + (size_t)b * (CH * HH * WW) + hw;
    float xv[CH];
#pragma unroll
    for (int c = 0; c < CH; c++) xv[c] = xp[(size_t)c * (HH * WW)];

#pragma unroll
    for (int di = 0; di < 2; di++) {
        int oi = i0 + di - 1;                        // output row
        if ((unsigned)oi >= 256u) continue;
#pragma unroll
        for (int dj = 0; dj < 2; dj++) {
            int oj = j0 + dj - 1;                    // output col
            if ((unsigned)oj >= 256u) continue;
            float wt = wi[di] * wj[dj];
            float4* dst = g_scratch4 + ((((size_t)b * 256 + oi) * 256 + oj) << 2);
#pragma unroll
            for (int k = 0; k < 4; k++) {
                atomicAdd(dst + k,
                          make_float4(xv[4*k + 0] * wt, xv[4*k + 1] * wt,
                                      xv[4*k + 2] * wt, xv[4*k + 3] * wt));
            }
        }
    }
}

// ---------------------------------------------------------------------------
// Kernel 3: transpose scratch [b][i][j][c] -> out [b][c][i][j].
// One block per (b,i) row: load 256*16 floats coalesced (float4), stage in
// smem with stride-17 padding (conflict-free strided reads), write 16
// coalesced 1KB channel segments. Fully overwrites d_out.
// ---------------------------------------------------------------------------
__global__ void __launch_bounds__(256) transpose_kernel(float* __restrict__ out) {
    __shared__ float s[256 * 17];
    int bi  = blockIdx.x;            // b*256 + i
    int tid = threadIdx.x;           // 0..255

    const float4* src = g_scratch4 + (size_t)bi * (256 * 4);   // 1024 float4 per row
#pragma unroll
    for (int it = 0; it < 4; it++) {
        int e = it * 256 + tid;      // float4 index within row
        float4 v = src[e];
        int j  = e >> 2;             // pixel column 0..255
        int cq = (e & 3) * 4;        // channel quad base 0/4/8/12
        float* sp = s + j * 17 + cq;
        sp[0] = v.x; sp[1] = v.y; sp[2] = v.z; sp[3] = v.w;
    }
    __syncthreads();

    int b = bi >> 8, i = bi & 255;
    float* op = out + ((size_t)b * CH * HH + i) * WW + tid;    // out[b][c][i][tid]
#pragma unroll
    for (int c = 0; c < CH; c++)
        op[(size_t)c * (HH * WW)] = s[tid * 17 + c];           // stride-17: conflict-free
}

// ---------------------------------------------------------------------------
extern "C" void kernel_launch(void* const* d_in, const int* in_sizes, int n_in,
                              void* d_out, int out_size)
{
    const float* x    = (const float*)d_in[0];
    const float* grid = (const float*)d_in[1];
    // Defensive: x has 8.39M elements, inv_grid 1.05M — pick by size.
    if (in_sizes[0] != BATCH * CH * HH * WW) {
        const float* t = x; x = grid; grid = t;
    }

    zero_kernel<<<SCRATCH_F4 / 256, 256>>>();
    scatter_kernel<<<NPTS / 256, 256>>>(x, (const float2*)grid);
    transpose_kernel<<<BATCH * HH, 256>>>((float*)d_out);
}